// round 9
// baseline (speedup 1.0000x reference)
#include <cuda_runtime.h>
#include <math.h>

#define BB 128
#define NN 256
#define MM (BB*NN)
#define KNBR 16
#define BN_SCALE_F 0.99999500003749969f

// ---------------- scratch (device globals; no allocation allowed) ----------
__device__ float g_U[MM * 256];
__device__ float g_V[MM * 256];
__device__ float g_h1[MM * 64];
__device__ float g_h2[MM * 128];
__device__ int   g_idx[MM * KNBR];
__device__ float g_p[BB * 256];

#define L3_SMEM_FLOATS 21056
#define L3_SMEM_BYTES  (L3_SMEM_FLOATS * 4)            // 84224
#define L2_SMEM_FLOATS (256*68 + 256)
#define L2_SMEM_BYTES  (L2_SMEM_FLOATS * 4)            // 70656
#define L1_SMEM_BYTES  ((256*8 + 256) * 4)             // 9216

// ---------------- whole-batch kNN, K=6 padded to 8 (round-1 body) ----------
__device__ __forceinline__ void knn6_body(const float* __restrict__ X,
                                          int* __restrict__ idx_out,
                                          int b, float* sm) {
    float* Xs  = sm;            // [256*8]
    float* sqs = sm + 256 * 8;  // [256]
    const int t = threadIdx.x;
    const float* Xb = X + (size_t)b * NN * 6;

    for (int e = t; e < NN * 6; e += 256)
        Xs[(e / 6) * 8 + (e % 6)] = Xb[e];
    Xs[t * 8 + 6] = 0.f; Xs[t * 8 + 7] = 0.f;
    __syncthreads();

    float4 xi0 = *reinterpret_cast<const float4*>(&Xs[t * 8]);
    float4 xi1 = *reinterpret_cast<const float4*>(&Xs[t * 8 + 4]);
    float sq = xi0.x*xi0.x + xi0.y*xi0.y + xi0.z*xi0.z + xi0.w*xi0.w
             + xi1.x*xi1.x + xi1.y*xi1.y;
    sqs[t] = sq;
    __syncthreads();

    float bd[KNBR]; int bj[KNBR];
    #pragma unroll
    for (int s = 0; s < KNBR; ++s) { bd[s] = INFINITY; bj[s] = -1; }

    for (int j = 0; j < NN; ++j) {
        float4 v0 = *reinterpret_cast<const float4*>(&Xs[j * 8]);
        float4 v1 = *reinterpret_cast<const float4*>(&Xs[j * 8 + 4]);
        float dot = xi0.x*v0.x + xi0.y*v0.y + xi0.z*v0.z + xi0.w*v0.w
                  + xi1.x*v1.x + xi1.y*v1.y;
        float d2 = sq + sqs[j] - 2.f * dot;
        if (j != t && d2 < bd[KNBR - 1]) {
            float nd = d2; int nj = j;
            #pragma unroll
            for (int s = 0; s < KNBR; ++s) {
                if (nd < bd[s]) {
                    float td = bd[s]; int tj = bj[s];
                    bd[s] = nd; bj[s] = nj; nd = td; nj = tj;
                }
            }
        }
    }
    #pragma unroll
    for (int s = 0; s < KNBR; ++s)
        idx_out[((size_t)b * NN + t) * KNBR + s] = bj[s];
}

// ---------------- whole-batch kNN, K=64 (xi in regs, xj broadcast) ---------
__device__ __forceinline__ void knn64_body(const float* __restrict__ X,
                                           int* __restrict__ idx_out,
                                           int b, float* sm) {
    float* Xs  = sm;               // [256*68] pitch 68 (272B rows, 16B aligned)
    float* sqs = sm + 256 * 68;    // [256]
    const int t = threadIdx.x;
    const float* Xb = X + (size_t)b * NN * 64;

    // staged float4 coalesced: 16 float4 per row
    for (int e4 = t; e4 < NN * 16; e4 += 256) {
        const int row = e4 >> 4, c4 = (e4 & 15) * 4;
        *reinterpret_cast<float4*>(&Xs[row * 68 + c4]) =
            *reinterpret_cast<const float4*>(&Xb[(size_t)row * 64 + c4]);
    }
    __syncthreads();

    float4 xi[16];
    #pragma unroll
    for (int q = 0; q < 16; ++q)
        xi[q] = *reinterpret_cast<const float4*>(&Xs[t * 68 + 4 * q]);
    float sq = 0.f;
    #pragma unroll
    for (int q = 0; q < 16; ++q)
        sq += xi[q].x*xi[q].x + xi[q].y*xi[q].y + xi[q].z*xi[q].z + xi[q].w*xi[q].w;
    sqs[t] = sq;
    __syncthreads();

    float bd[KNBR]; int bj[KNBR];
    #pragma unroll
    for (int s = 0; s < KNBR; ++s) { bd[s] = INFINITY; bj[s] = -1; }

    for (int j = 0; j < NN; ++j) {
        const float4* xj = reinterpret_cast<const float4*>(&Xs[j * 68]);
        float dx = 0.f, dy = 0.f, dz = 0.f, dw = 0.f;
        #pragma unroll
        for (int q = 0; q < 16; ++q) {
            float4 v = xj[q];                       // broadcast LDS.128
            dx += xi[q].x * v.x;
            dy += xi[q].y * v.y;
            dz += xi[q].z * v.z;
            dw += xi[q].w * v.w;
        }
        float d2 = sq + sqs[j] - 2.f * ((dx + dy) + (dz + dw));
        if (j != t && d2 < bd[KNBR - 1]) {
            float nd = d2; int nj = j;
            #pragma unroll
            for (int s = 0; s < KNBR; ++s) {
                if (nd < bd[s]) {
                    float td = bd[s]; int tj = bj[s];
                    bd[s] = nd; bj[s] = nj; nd = td; nj = tj;
                }
            }
        }
    }
    #pragma unroll
    for (int s = 0; s < KNBR; ++s)
        idx_out[((size_t)b * NN + t) * KNBR + s] = bj[s];
}

// ============ tiled kNN body for K=128 (round-8, unchanged) ===============
__device__ __forceinline__ void knn128_tile_body(const float* __restrict__ X,
                                                 int* __restrict__ idx_out,
                                                 int bid, float* sm) {
    constexpr int K = 128;
    float* BsD = sm;              // [2][8][260]
    float* sqb = sm + 4160;       // [256]
    float* D2s = sm + 4416;       // [64][260]
    const int b  = bid >> 2;
    const int m0 = (bid & 3) * 64;
    const int t  = threadIdx.x;
    const float* Xb = X + (size_t)b * NN * K;
    const int tn = t & 31, tm = t >> 5;

    float acc[8][8] = {};
    float snorm = 0.f;

    auto stage = [&](int buf, const float4& a, const float4& c) {
        float* B = BsD + buf * 2080;
        B[0 * 260 + t] = a.x; B[1 * 260 + t] = a.y;
        B[2 * 260 + t] = a.z; B[3 * 260 + t] = a.w;
        B[4 * 260 + t] = c.x; B[5 * 260 + t] = c.y;
        B[6 * 260 + t] = c.z; B[7 * 260 + t] = c.w;
    };
    auto compute = [&](int pb) {
        const float* B = BsD + pb * 2080;
        #pragma unroll
        for (int k = 0; k < 8; ++k) {
            float4 a0 = *reinterpret_cast<const float4*>(&B[k * 260 + m0 + tm * 8]);
            float4 a1 = *reinterpret_cast<const float4*>(&B[k * 260 + m0 + tm * 8 + 4]);
            float4 b0 = *reinterpret_cast<const float4*>(&B[k * 260 + tn * 4]);
            float4 b1 = *reinterpret_cast<const float4*>(&B[k * 260 + 128 + tn * 4]);
            float av[8] = {a0.x, a0.y, a0.z, a0.w, a1.x, a1.y, a1.z, a1.w};
            float bv[8] = {b0.x, b0.y, b0.z, b0.w, b1.x, b1.y, b1.z, b1.w};
            #pragma unroll
            for (int i = 0; i < 8; ++i) {
                #pragma unroll
                for (int c = 0; c < 8; ++c)
                    acc[i][c] += av[i] * bv[c];
            }
        }
    };

    float4 v0 = *reinterpret_cast<const float4*>(&Xb[(size_t)t * K]);
    float4 v1 = *reinterpret_cast<const float4*>(&Xb[(size_t)t * K + 4]);
    snorm += v0.x*v0.x + v0.y*v0.y + v0.z*v0.z + v0.w*v0.w
           + v1.x*v1.x + v1.y*v1.y + v1.z*v1.z + v1.w*v1.w;
    stage(0, v0, v1);
    __syncthreads();

    const int NCH = K / 8;
    for (int ci = 1; ci < NCH; ++ci) {
        float4 n0_ = *reinterpret_cast<const float4*>(&Xb[(size_t)t * K + ci * 8]);
        float4 n1_ = *reinterpret_cast<const float4*>(&Xb[(size_t)t * K + ci * 8 + 4]);
        compute((ci - 1) & 1);
        snorm += n0_.x*n0_.x + n0_.y*n0_.y + n0_.z*n0_.z + n0_.w*n0_.w
               + n1_.x*n1_.x + n1_.y*n1_.y + n1_.z*n1_.z + n1_.w*n1_.w;
        stage(ci & 1, n0_, n1_);
        __syncthreads();
    }
    compute((NCH - 1) & 1);
    sqb[t] = snorm;
    __syncthreads();

    #pragma unroll
    for (int i = 0; i < 8; ++i) {
        const int row = tm * 8 + i;
        const float si = sqb[m0 + row];
        float4 o0, o1;
        o0.x = si + sqb[tn*4+0]     - 2.f * acc[i][0];
        o0.y = si + sqb[tn*4+1]     - 2.f * acc[i][1];
        o0.z = si + sqb[tn*4+2]     - 2.f * acc[i][2];
        o0.w = si + sqb[tn*4+3]     - 2.f * acc[i][3];
        o1.x = si + sqb[128+tn*4+0] - 2.f * acc[i][4];
        o1.y = si + sqb[128+tn*4+1] - 2.f * acc[i][5];
        o1.z = si + sqb[128+tn*4+2] - 2.f * acc[i][6];
        o1.w = si + sqb[128+tn*4+3] - 2.f * acc[i][7];
        *reinterpret_cast<float4*>(&D2s[row * 260 + tn * 4])       = o0;
        *reinterpret_cast<float4*>(&D2s[row * 260 + 128 + tn * 4]) = o1;
    }
    __syncthreads();

    if (t < 64) D2s[t * 260 + m0 + t] = INFINITY;   // poison self
    __syncthreads();

    const int r = t >> 2, q = t & 3;
    float bd[KNBR]; int bj[KNBR];
    #pragma unroll
    for (int s = 0; s < KNBR; ++s) { bd[s] = INFINITY; bj[s] = -1; }

    for (int j4 = 0; j4 < 16; ++j4) {
        float4 v = *reinterpret_cast<const float4*>(&D2s[r * 260 + q * 64 + j4 * 4]);
        float dv[4] = {v.x, v.y, v.z, v.w};
        #pragma unroll
        for (int e = 0; e < 4; ++e) {
            const float d2 = dv[e];
            if (d2 < bd[KNBR - 1]) {
                const int j = q * 64 + j4 * 4 + e;
                float nd = d2; int nj = j;
                #pragma unroll
                for (int s = 0; s < KNBR; ++s) {
                    if (nd < bd[s]) {
                        float td = bd[s]; int tj = bj[s];
                        bd[s] = nd; bj[s] = nj; nd = td; nj = tj;
                    }
                }
            }
        }
    }
    __syncthreads();
    float* sd = D2s;
    int*   si = reinterpret_cast<int*>(D2s + 4096);
    #pragma unroll
    for (int s = 0; s < KNBR; ++s) {
        sd[(r * 4 + q) * 16 + s] = bd[s];
        si[(r * 4 + q) * 16 + s] = bj[s];
    }
    __syncthreads();

    if (q == 0) {
        float fd[KNBR]; int fj[KNBR];
        #pragma unroll
        for (int s = 0; s < KNBR; ++s) { fd[s] = INFINITY; fj[s] = -1; }
        for (int qq = 0; qq < 4; ++qq) {
            for (int s = 0; s < KNBR; ++s) {
                float d = sd[(r * 4 + qq) * 16 + s];
                if (!(d < fd[KNBR - 1])) break;
                int nj = si[(r * 4 + qq) * 16 + s];
                float nd = d;
                #pragma unroll
                for (int s2 = 0; s2 < KNBR; ++s2) {
                    if (nd < fd[s2]) {
                        float td = fd[s2]; int tj = fj[s2];
                        fd[s2] = nd; fj[s2] = nj; nd = td; nj = tj;
                    }
                }
            }
        }
        #pragma unroll
        for (int s = 0; s < KNBR; ++s)
            idx_out[((size_t)b * NN + m0 + r) * KNBR + s] = fj[s];
    }
}

// ---------------- layer-1 U/V body (K=6, C=64): 32 points per block --------
__device__ __forceinline__ void uv1_body(const float* __restrict__ X,
                                         const float* __restrict__ W,
                                         float* __restrict__ U,
                                         float* __restrict__ V,
                                         int bid2, float* sm) {
    float* Ws = sm;
    const int t = threadIdx.x;
    for (int e = t; e < 12 * 64; e += 256) Ws[e] = W[e];
    __syncthreads();
    const int c = t & 63, pp = t >> 6;
    const int m0 = bid2 * 32;
    #pragma unroll
    for (int i = 0; i < 8; ++i) {
        const int m = m0 + i * 4 + pp;
        const float* x = X + (size_t)m * 6;
        float u = 0.f, v = 0.f;
        #pragma unroll
        for (int d = 0; d < 6; ++d) {
            float xd = x[d];
            u += xd * Ws[d * 64 + c];
            v += xd * Ws[(6 + d) * 64 + c];
        }
        U[(size_t)m * 64 + c] = u;
        V[(size_t)m * 64 + c] = v;
    }
}

// ---- U/V GEMM body: BM=128 BN=128 BK=8, 8x8/thread, double-buffered -------
template<int K>
__device__ __forceinline__ void uv_body8(const float* __restrict__ X,
                                         const float* __restrict__ W,
                                         const int C, float* __restrict__ U,
                                         float* __restrict__ V,
                                         int bx, int by, float* sm) {
    float* As = sm;
    float* Wt = sm + 2112;
    const int t = threadIdx.x;
    const int m0 = bx * 128;
    const int nt = C / 128;
    const bool isU = by < nt;
    const int n0 = (isU ? by : by - nt) * 128;
    const float* Wb = W + (isU ? (size_t)0 : (size_t)K * C);
    float* Out = isU ? U : V;

    const int am = t >> 1, ak = (t & 1) * 4;
    const int wk = t >> 5, wn = (t & 31) * 4;
    const int tx = t & 15, ty = t >> 4;

    float acc[8][8] = {};

    auto stage = [&](int buf, const float4& xa, const float4& wa) {
        float* A = As + buf * 1056;
        A[(ak + 0) * 132 + am] = xa.x; A[(ak + 1) * 132 + am] = xa.y;
        A[(ak + 2) * 132 + am] = xa.z; A[(ak + 3) * 132 + am] = xa.w;
        *reinterpret_cast<float4*>(&Wt[buf * 1056 + wk * 132 + wn]) = wa;
    };
    auto compute = [&](int pb) {
        const float* A = As + pb * 1056;
        const float* Wp = Wt + pb * 1056;
        #pragma unroll
        for (int k = 0; k < 8; ++k) {
            float4 a0 = *reinterpret_cast<const float4*>(&A[k * 132 + ty * 8]);
            float4 a1 = *reinterpret_cast<const float4*>(&A[k * 132 + ty * 8 + 4]);
            float4 b0 = *reinterpret_cast<const float4*>(&Wp[k * 132 + tx * 4]);
            float4 b1 = *reinterpret_cast<const float4*>(&Wp[k * 132 + 64 + tx * 4]);
            float av[8] = {a0.x, a0.y, a0.z, a0.w, a1.x, a1.y, a1.z, a1.w};
            float bv[8] = {b0.x, b0.y, b0.z, b0.w, b1.x, b1.y, b1.z, b1.w};
            #pragma unroll
            for (int i = 0; i < 8; ++i) {
                #pragma unroll
                for (int c = 0; c < 8; ++c)
                    acc[i][c] += av[i] * bv[c];
            }
        }
    };

    float4 xa = *reinterpret_cast<const float4*>(&X[(size_t)(m0 + am) * K + ak]);
    float4 wa = *reinterpret_cast<const float4*>(&Wb[(size_t)wk * C + n0 + wn]);
    stage(0, xa, wa);
    __syncthreads();

    const int NCH = K / 8;
    for (int ci = 1; ci < NCH; ++ci) {
        float4 xn = *reinterpret_cast<const float4*>(
            &X[(size_t)(m0 + am) * K + ci * 8 + ak]);
        float4 wnx = *reinterpret_cast<const float4*>(
            &Wb[(size_t)(ci * 8 + wk) * C + n0 + wn]);
        compute((ci - 1) & 1);
        stage(ci & 1, xn, wnx);
        __syncthreads();
    }
    compute((NCH - 1) & 1);

    #pragma unroll
    for (int i = 0; i < 8; ++i) {
        float* dst = &Out[(size_t)(m0 + ty * 8 + i) * C + n0 + tx * 4];
        *reinterpret_cast<float4*>(dst) =
            make_float4(acc[i][0], acc[i][1], acc[i][2], acc[i][3]);
        *reinterpret_cast<float4*>(dst + 64) =
            make_float4(acc[i][4], acc[i][5], acc[i][6], acc[i][7]);
    }
}

// ---------------- fat kernels ----------------------------------------------
__global__ __launch_bounds__(256)
void fatL1(const float* __restrict__ x, const float* __restrict__ W1,
           int* __restrict__ idx, float* __restrict__ U, float* __restrict__ V) {
    extern __shared__ float sm[];
    const int bid = blockIdx.x;
    if (bid < 128) knn6_body(x, idx, bid, sm);
    else           uv1_body(x, W1, U, V, bid - 128, sm);
}

__global__ __launch_bounds__(256, 2)
void fatL2(const float* __restrict__ h1, const float* __restrict__ W2,
           int* __restrict__ idx, float* __restrict__ U, float* __restrict__ V) {
    extern __shared__ float sm[];
    const int bid = blockIdx.x;
    if (bid < 128) knn64_body(h1, idx, bid, sm);
    else {
        const int b2 = bid - 128;                  // [0, 512)
        uv_body8<64>(h1, W2, 128, U, V, b2 & 255, b2 >> 8, sm);
    }
}

__global__ __launch_bounds__(256)
void fatL3(const float* __restrict__ h2, const float* __restrict__ W3,
           int* __restrict__ idx, float* __restrict__ U, float* __restrict__ V) {
    extern __shared__ float sm[];
    const int bid = blockIdx.x;
    if (bid < 512) knn128_tile_body(h2, idx, bid, sm);
    else {
        const int b2 = bid - 512;                  // [0, 1024)
        uv_body8<128>(h2, W3, 256, U, V, b2 & 255, b2 >> 8, sm);
    }
}

// ---------------- neighbor aggregation + BN + ReLU -------------------------
template<int C>
__global__ __launch_bounds__(256)
void agg_kernel(const float* __restrict__ U, const float* __restrict__ V,
                const int* __restrict__ idx, const float* __restrict__ bias,
                const float* __restrict__ g, const float* __restrict__ be,
                float* __restrict__ H) {
    constexpr int PPB = 256 / C;
    __shared__ int sidx[PPB * KNBR];
    const int p0 = blockIdx.x * PPB;
    const int t = threadIdx.x;
    if (t < PPB * KNBR) sidx[t] = idx[(size_t)p0 * KNBR + t] * C;
    __syncthreads();
    const int lp = t / C, c = t % C;
    const int pt = p0 + lp;
    const int b = pt >> 8;
    const float* VbC = V + ((size_t)(b << 8)) * C + c;
    float u = U[(size_t)pt * C + c];
    float v = V[(size_t)pt * C + c];
    float mx = -INFINITY, mn = INFINITY;
    #pragma unroll
    for (int k = 0; k < KNBR; ++k) {
        float val = VbC[sidx[lp * KNBR + k]];
        mx = fmaxf(mx, val);
        mn = fminf(mn, val);
    }
    float a = g[c] * BN_SCALE_F;
    float m = (a >= 0.f) ? mx : mn;
    float h = fmaf(a, u - v + m + bias[c], be[c]);
    H[(size_t)pt * C + c] = fmaxf(h, 0.f);
}

template<int C>
__global__ __launch_bounds__(256)
void agg_pool_kernel(const float* __restrict__ U, const float* __restrict__ V,
                     const int* __restrict__ idx, const float* __restrict__ bias,
                     const float* __restrict__ g, const float* __restrict__ be,
                     int* __restrict__ P) {
    __shared__ int sidx[KNBR];
    const int pt = blockIdx.x;
    const int t = threadIdx.x;
    if (t < KNBR) sidx[t] = idx[(size_t)pt * KNBR + t] * C;
    __syncthreads();
    const int c = t;
    const int b = pt >> 8;
    const float* VbC = V + ((size_t)(b << 8)) * C + c;
    float u = U[(size_t)pt * C + c];
    float v = V[(size_t)pt * C + c];
    float mx = -INFINITY, mn = INFINITY;
    #pragma unroll
    for (int k = 0; k < KNBR; ++k) {
        float val = VbC[sidx[k]];
        mx = fmaxf(mx, val);
        mn = fminf(mn, val);
    }
    float a = g[c] * BN_SCALE_F;
    float m = (a >= 0.f) ? mx : mn;
    float h = fmaxf(fmaf(a, u - v + m + bias[c], be[c]), 0.f);
    atomicMax(&P[b * C + c], __float_as_int(h));   // h >= 0
}

// ---------------- FC head --------------------------------------------------
__global__ __launch_bounds__(256)
void head_kernel(const float* __restrict__ Pp, const float* __restrict__ Wf1,
                 const float* __restrict__ bf1, const float* __restrict__ gf,
                 const float* __restrict__ bef, const float* __restrict__ Wf2,
                 const float* __restrict__ bf2, float* __restrict__ out) {
    __shared__ float ps[256];
    __shared__ float fs[128];
    const int b = blockIdx.x, t = threadIdx.x;
    ps[t] = Pp[b * 256 + t];
    __syncthreads();
    if (t < 128) {
        float acc = bf1[t];
        for (int r = 0; r < 256; ++r) acc += ps[r] * Wf1[r * 128 + t];
        float a = gf[t] * BN_SCALE_F;
        fs[t] = fmaxf(fmaf(a, acc, bef[t]), 0.f);
    }
    __syncthreads();
    if (t < 12) {
        float acc = bf2[t];
        for (int j = 0; j < 128; ++j) acc += fs[j] * Wf2[j * 12 + t];
        out[b * 12 + t] = acc;
    }
}

// ---------------- launch ----------------------------------------------------
extern "C" void kernel_launch(void* const* d_in, const int* in_sizes, int n_in,
                              void* d_out, int out_size) {
    const float* x   = (const float*)d_in[0];
    const float* W1  = (const float*)d_in[1];
    const float* b1  = (const float*)d_in[2];
    const float* g1  = (const float*)d_in[3];
    const float* be1 = (const float*)d_in[4];
    const float* W2  = (const float*)d_in[5];
    const float* b2  = (const float*)d_in[6];
    const float* g2  = (const float*)d_in[7];
    const float* be2 = (const float*)d_in[8];
    const float* W3  = (const float*)d_in[9];
    const float* b3  = (const float*)d_in[10];
    const float* g3  = (const float*)d_in[11];
    const float* be3 = (const float*)d_in[12];
    const float* Wf1 = (const float*)d_in[13];
    const float* bf1 = (const float*)d_in[14];
    const float* gf  = (const float*)d_in[15];
    const float* bef = (const float*)d_in[16];
    const float* Wf2 = (const float*)d_in[17];
    const float* bf2 = (const float*)d_in[18];
    float* out = (float*)d_out;

    float *U, *V, *h1, *h2, *p;
    int* idx;
    cudaGetSymbolAddress((void**)&U,  g_U);
    cudaGetSymbolAddress((void**)&V,  g_V);
    cudaGetSymbolAddress((void**)&h1, g_h1);
    cudaGetSymbolAddress((void**)&h2, g_h2);
    cudaGetSymbolAddress((void**)&idx, g_idx);
    cudaGetSymbolAddress((void**)&p,  g_p);

    cudaFuncSetAttribute(fatL1, cudaFuncAttributeMaxDynamicSharedMemorySize, L1_SMEM_BYTES);
    cudaFuncSetAttribute(fatL2, cudaFuncAttributeMaxDynamicSharedMemorySize, L2_SMEM_BYTES);
    cudaFuncSetAttribute(fatL3, cudaFuncAttributeMaxDynamicSharedMemorySize, L3_SMEM_BYTES);

    // ---- layer 1: D=6 -> C=64 ----
    fatL1<<<128 + 1024, 256, L1_SMEM_BYTES>>>(x, W1, idx, U, V);
    agg_kernel<64><<<MM / 4, 256>>>(U, V, idx, b1, g1, be1, h1);

    // ---- layer 2: D=64 -> C=128 ----
    fatL2<<<128 + 512, 256, L2_SMEM_BYTES>>>(h1, W2, idx, U, V);
    agg_kernel<128><<<MM / 2, 256>>>(U, V, idx, b2, g2, be2, h2);

    // ---- layer 3: D=128 -> C=256 ----
    fatL3<<<512 + 1024, 256, L3_SMEM_BYTES>>>(h2, W3, idx, U, V);
    cudaMemsetAsync(p, 0, BB * 256 * sizeof(float));
    agg_pool_kernel<256><<<MM, 256>>>(U, V, idx, b3, g3, be3, (int*)p);

    // ---- head ----
    head_kernel<<<BB, 256>>>(p, Wf1, bf1, gf, bef, Wf2, bf2, out);
}

// round 10
// speedup vs baseline: 1.0453x; 1.0453x over previous
#include <cuda_runtime.h>
#include <math.h>

#define BB 128
#define NN 256
#define MM (BB*NN)
#define KNBR 16
#define BN_SCALE_F 0.99999500003749969f

// ---------------- scratch (device globals; no allocation allowed) ----------
__device__ float g_U[MM * 256];
__device__ float g_V[MM * 256];
__device__ float g_h1[MM * 64];
__device__ float g_h2[MM * 128];
__device__ int   g_idx[MM * KNBR];
__device__ float g_p[BB * 256];

#define FAT_SMEM_FLOATS 21056
#define FAT_SMEM_BYTES  (FAT_SMEM_FLOATS * 4)   // 84224 (fatL2/fatL3)
#define L1_SMEM_BYTES   ((256*8 + 256) * 4)     // 9216  (fatL1)

// ---------------- whole-batch kNN, K=6 padded to 8 (round-1 proven) --------
__device__ __forceinline__ void knn6_body(const float* __restrict__ X,
                                          int* __restrict__ idx_out,
                                          int b, float* sm) {
    float* Xs  = sm;            // [256*8]
    float* sqs = sm + 256 * 8;  // [256]
    const int t = threadIdx.x;
    const float* Xb = X + (size_t)b * NN * 6;

    for (int e = t; e < NN * 6; e += 256)
        Xs[(e / 6) * 8 + (e % 6)] = Xb[e];
    Xs[t * 8 + 6] = 0.f; Xs[t * 8 + 7] = 0.f;
    __syncthreads();

    float4 xi0 = *reinterpret_cast<const float4*>(&Xs[t * 8]);
    float4 xi1 = *reinterpret_cast<const float4*>(&Xs[t * 8 + 4]);
    float sq = xi0.x*xi0.x + xi0.y*xi0.y + xi0.z*xi0.z + xi0.w*xi0.w
             + xi1.x*xi1.x + xi1.y*xi1.y;
    sqs[t] = sq;
    __syncthreads();

    float bd[KNBR]; int bj[KNBR];
    #pragma unroll
    for (int s = 0; s < KNBR; ++s) { bd[s] = INFINITY; bj[s] = -1; }

    for (int j = 0; j < NN; ++j) {
        float4 v0 = *reinterpret_cast<const float4*>(&Xs[j * 8]);
        float4 v1 = *reinterpret_cast<const float4*>(&Xs[j * 8 + 4]);
        float dot = xi0.x*v0.x + xi0.y*v0.y + xi0.z*v0.z + xi0.w*v0.w
                  + xi1.x*v1.x + xi1.y*v1.y;
        float d2 = sq + sqs[j] - 2.f * dot;
        if (j != t && d2 < bd[KNBR - 1]) {
            float nd = d2; int nj = j;
            #pragma unroll
            for (int s = 0; s < KNBR; ++s) {
                if (nd < bd[s]) {
                    float td = bd[s]; int tj = bj[s];
                    bd[s] = nd; bj[s] = nj; nd = td; nj = tj;
                }
            }
        }
    }
    #pragma unroll
    for (int s = 0; s < KNBR; ++s)
        idx_out[((size_t)b * NN + t) * KNBR + s] = bj[s];
}

// ============ tiled kNN body (round-8): dist GEMM + 4-way select ===========
template<int K>
__device__ __forceinline__ void knn_tile_body(const float* __restrict__ X,
                                              int* __restrict__ idx_out,
                                              int bid, float* sm) {
    float* BsD = sm;              // [2][8][260]
    float* sqb = sm + 4160;       // [256]
    float* D2s = sm + 4416;       // [64][260]
    const int b  = bid >> 2;
    const int m0 = (bid & 3) * 64;
    const int t  = threadIdx.x;
    const float* Xb = X + (size_t)b * NN * K;
    const int tn = t & 31, tm = t >> 5;

    float acc[8][8] = {};
    float snorm = 0.f;

    auto stage = [&](int buf, const float4& a, const float4& c) {
        float* B = BsD + buf * 2080;
        B[0 * 260 + t] = a.x; B[1 * 260 + t] = a.y;
        B[2 * 260 + t] = a.z; B[3 * 260 + t] = a.w;
        B[4 * 260 + t] = c.x; B[5 * 260 + t] = c.y;
        B[6 * 260 + t] = c.z; B[7 * 260 + t] = c.w;
    };
    auto compute = [&](int pb) {
        const float* B = BsD + pb * 2080;
        #pragma unroll
        for (int k = 0; k < 8; ++k) {
            float4 a0 = *reinterpret_cast<const float4*>(&B[k * 260 + m0 + tm * 8]);
            float4 a1 = *reinterpret_cast<const float4*>(&B[k * 260 + m0 + tm * 8 + 4]);
            float4 b0 = *reinterpret_cast<const float4*>(&B[k * 260 + tn * 4]);
            float4 b1 = *reinterpret_cast<const float4*>(&B[k * 260 + 128 + tn * 4]);
            float av[8] = {a0.x, a0.y, a0.z, a0.w, a1.x, a1.y, a1.z, a1.w};
            float bv[8] = {b0.x, b0.y, b0.z, b0.w, b1.x, b1.y, b1.z, b1.w};
            #pragma unroll
            for (int i = 0; i < 8; ++i) {
                #pragma unroll
                for (int c = 0; c < 8; ++c)
                    acc[i][c] += av[i] * bv[c];
            }
        }
    };

    float4 v0 = *reinterpret_cast<const float4*>(&Xb[(size_t)t * K]);
    float4 v1 = *reinterpret_cast<const float4*>(&Xb[(size_t)t * K + 4]);
    snorm += v0.x*v0.x + v0.y*v0.y + v0.z*v0.z + v0.w*v0.w
           + v1.x*v1.x + v1.y*v1.y + v1.z*v1.z + v1.w*v1.w;
    stage(0, v0, v1);
    __syncthreads();

    const int NCH = K / 8;
    for (int ci = 1; ci < NCH; ++ci) {
        float4 n0_ = *reinterpret_cast<const float4*>(&Xb[(size_t)t * K + ci * 8]);
        float4 n1_ = *reinterpret_cast<const float4*>(&Xb[(size_t)t * K + ci * 8 + 4]);
        compute((ci - 1) & 1);
        snorm += n0_.x*n0_.x + n0_.y*n0_.y + n0_.z*n0_.z + n0_.w*n0_.w
               + n1_.x*n1_.x + n1_.y*n1_.y + n1_.z*n1_.z + n1_.w*n1_.w;
        stage(ci & 1, n0_, n1_);
        __syncthreads();
    }
    compute((NCH - 1) & 1);
    sqb[t] = snorm;
    __syncthreads();

    #pragma unroll
    for (int i = 0; i < 8; ++i) {
        const int row = tm * 8 + i;
        const float si = sqb[m0 + row];
        float4 o0, o1;
        o0.x = si + sqb[tn*4+0]     - 2.f * acc[i][0];
        o0.y = si + sqb[tn*4+1]     - 2.f * acc[i][1];
        o0.z = si + sqb[tn*4+2]     - 2.f * acc[i][2];
        o0.w = si + sqb[tn*4+3]     - 2.f * acc[i][3];
        o1.x = si + sqb[128+tn*4+0] - 2.f * acc[i][4];
        o1.y = si + sqb[128+tn*4+1] - 2.f * acc[i][5];
        o1.z = si + sqb[128+tn*4+2] - 2.f * acc[i][6];
        o1.w = si + sqb[128+tn*4+3] - 2.f * acc[i][7];
        *reinterpret_cast<float4*>(&D2s[row * 260 + tn * 4])       = o0;
        *reinterpret_cast<float4*>(&D2s[row * 260 + 128 + tn * 4]) = o1;
    }
    __syncthreads();

    if (t < 64) D2s[t * 260 + m0 + t] = INFINITY;   // poison self
    __syncthreads();

    const int r = t >> 2, q = t & 3;
    float bd[KNBR]; int bj[KNBR];
    #pragma unroll
    for (int s = 0; s < KNBR; ++s) { bd[s] = INFINITY; bj[s] = -1; }

    for (int j4 = 0; j4 < 16; ++j4) {
        float4 v = *reinterpret_cast<const float4*>(&D2s[r * 260 + q * 64 + j4 * 4]);
        float dv[4] = {v.x, v.y, v.z, v.w};
        #pragma unroll
        for (int e = 0; e < 4; ++e) {
            const float d2 = dv[e];
            if (d2 < bd[KNBR - 1]) {
                const int j = q * 64 + j4 * 4 + e;
                float nd = d2; int nj = j;
                #pragma unroll
                for (int s = 0; s < KNBR; ++s) {
                    if (nd < bd[s]) {
                        float td = bd[s]; int tj = bj[s];
                        bd[s] = nd; bj[s] = nj; nd = td; nj = tj;
                    }
                }
            }
        }
    }
    __syncthreads();
    float* sd = D2s;
    int*   si = reinterpret_cast<int*>(D2s + 4096);
    #pragma unroll
    for (int s = 0; s < KNBR; ++s) {
        sd[(r * 4 + q) * 16 + s] = bd[s];
        si[(r * 4 + q) * 16 + s] = bj[s];
    }
    __syncthreads();

    if (q == 0) {
        float fd[KNBR]; int fj[KNBR];
        #pragma unroll
        for (int s = 0; s < KNBR; ++s) { fd[s] = INFINITY; fj[s] = -1; }
        // ascending chunk order, each sorted ascending; strict < insert keeps
        // the lower-index candidate on exact ties (lax.top_k semantics).
        for (int qq = 0; qq < 4; ++qq) {
            for (int s = 0; s < KNBR; ++s) {
                float d = sd[(r * 4 + qq) * 16 + s];
                if (!(d < fd[KNBR - 1])) break;
                int nj = si[(r * 4 + qq) * 16 + s];
                float nd = d;
                #pragma unroll
                for (int s2 = 0; s2 < KNBR; ++s2) {
                    if (nd < fd[s2]) {
                        float td = fd[s2]; int tj = fj[s2];
                        fd[s2] = nd; fj[s2] = nj; nd = td; nj = tj;
                    }
                }
            }
        }
        #pragma unroll
        for (int s = 0; s < KNBR; ++s)
            idx_out[((size_t)b * NN + m0 + r) * KNBR + s] = fj[s];
    }
}

// ---------------- layer-1 U/V body (K=6, C=64): 32 points per block --------
__device__ __forceinline__ void uv1_body(const float* __restrict__ X,
                                         const float* __restrict__ W,
                                         float* __restrict__ U,
                                         float* __restrict__ V,
                                         int bid2, float* sm) {
    float* Ws = sm;
    const int t = threadIdx.x;
    for (int e = t; e < 12 * 64; e += 256) Ws[e] = W[e];
    __syncthreads();
    const int c = t & 63, pp = t >> 6;
    const int m0 = bid2 * 32;
    #pragma unroll
    for (int i = 0; i < 8; ++i) {
        const int m = m0 + i * 4 + pp;
        const float* x = X + (size_t)m * 6;
        float u = 0.f, v = 0.f;
        #pragma unroll
        for (int d = 0; d < 6; ++d) {
            float xd = x[d];
            u += xd * Ws[d * 64 + c];
            v += xd * Ws[(6 + d) * 64 + c];
        }
        U[(size_t)m * 64 + c] = u;
        V[(size_t)m * 64 + c] = v;
    }
}

// ---- U/V GEMM body: BM=128 BN=128 BK=8, 8x8/thread, double-buffered -------
template<int K>
__device__ __forceinline__ void uv_body8(const float* __restrict__ X,
                                         const float* __restrict__ W,
                                         const int C, float* __restrict__ U,
                                         float* __restrict__ V,
                                         int bx, int by, float* sm) {
    float* As = sm;
    float* Wt = sm + 2112;
    const int t = threadIdx.x;
    const int m0 = bx * 128;
    const int nt = C / 128;
    const bool isU = by < nt;
    const int n0 = (isU ? by : by - nt) * 128;
    const float* Wb = W + (isU ? (size_t)0 : (size_t)K * C);
    float* Out = isU ? U : V;

    const int am = t >> 1, ak = (t & 1) * 4;
    const int wk = t >> 5, wn = (t & 31) * 4;
    const int tx = t & 15, ty = t >> 4;

    float acc[8][8] = {};

    auto stage = [&](int buf, const float4& xa, const float4& wa) {
        float* A = As + buf * 1056;
        A[(ak + 0) * 132 + am] = xa.x; A[(ak + 1) * 132 + am] = xa.y;
        A[(ak + 2) * 132 + am] = xa.z; A[(ak + 3) * 132 + am] = xa.w;
        *reinterpret_cast<float4*>(&Wt[buf * 1056 + wk * 132 + wn]) = wa;
    };
    auto compute = [&](int pb) {
        const float* A = As + pb * 1056;
        const float* Wp = Wt + pb * 1056;
        #pragma unroll
        for (int k = 0; k < 8; ++k) {
            float4 a0 = *reinterpret_cast<const float4*>(&A[k * 132 + ty * 8]);
            float4 a1 = *reinterpret_cast<const float4*>(&A[k * 132 + ty * 8 + 4]);
            float4 b0 = *reinterpret_cast<const float4*>(&Wp[k * 132 + tx * 4]);
            float4 b1 = *reinterpret_cast<const float4*>(&Wp[k * 132 + 64 + tx * 4]);
            float av[8] = {a0.x, a0.y, a0.z, a0.w, a1.x, a1.y, a1.z, a1.w};
            float bv[8] = {b0.x, b0.y, b0.z, b0.w, b1.x, b1.y, b1.z, b1.w};
            #pragma unroll
            for (int i = 0; i < 8; ++i) {
                #pragma unroll
                for (int c = 0; c < 8; ++c)
                    acc[i][c] += av[i] * bv[c];
            }
        }
    };

    float4 xa = *reinterpret_cast<const float4*>(&X[(size_t)(m0 + am) * K + ak]);
    float4 wa = *reinterpret_cast<const float4*>(&Wb[(size_t)wk * C + n0 + wn]);
    stage(0, xa, wa);
    __syncthreads();

    const int NCH = K / 8;
    for (int ci = 1; ci < NCH; ++ci) {
        float4 xn = *reinterpret_cast<const float4*>(
            &X[(size_t)(m0 + am) * K + ci * 8 + ak]);
        float4 wnx = *reinterpret_cast<const float4*>(
            &Wb[(size_t)(ci * 8 + wk) * C + n0 + wn]);
        compute((ci - 1) & 1);
        stage(ci & 1, xn, wnx);
        __syncthreads();
    }
    compute((NCH - 1) & 1);

    #pragma unroll
    for (int i = 0; i < 8; ++i) {
        float* dst = &Out[(size_t)(m0 + ty * 8 + i) * C + n0 + tx * 4];
        *reinterpret_cast<float4*>(dst) =
            make_float4(acc[i][0], acc[i][1], acc[i][2], acc[i][3]);
        *reinterpret_cast<float4*>(dst + 64) =
            make_float4(acc[i][4], acc[i][5], acc[i][6], acc[i][7]);
    }
}

// ---------------- fat kernels ----------------------------------------------
__global__ __launch_bounds__(256)
void fatL1(const float* __restrict__ x, const float* __restrict__ W1,
           int* __restrict__ idx, float* __restrict__ U, float* __restrict__ V) {
    extern __shared__ float sm[];
    const int bid = blockIdx.x;
    if (bid < 128) knn6_body(x, idx, bid, sm);
    else           uv1_body(x, W1, U, V, bid - 128, sm);
}

__global__ __launch_bounds__(256)
void fatL2(const float* __restrict__ h1, const float* __restrict__ W2,
           int* __restrict__ idx, float* __restrict__ U, float* __restrict__ V) {
    extern __shared__ float sm[];
    const int bid = blockIdx.x;
    if (bid < 512) knn_tile_body<64>(h1, idx, bid, sm);
    else {
        const int b2 = bid - 512;                  // [0, 512)
        uv_body8<64>(h1, W2, 128, U, V, b2 & 255, b2 >> 8, sm);
    }
}

__global__ __launch_bounds__(256)
void fatL3(const float* __restrict__ h2, const float* __restrict__ W3,
           int* __restrict__ idx, float* __restrict__ U, float* __restrict__ V) {
    extern __shared__ float sm[];
    const int bid = blockIdx.x;
    if (bid < 512) knn_tile_body<128>(h2, idx, bid, sm);
    else {
        const int b2 = bid - 512;                  // [0, 1024)
        uv_body8<128>(h2, W3, 256, U, V, b2 & 255, b2 >> 8, sm);
    }
}

// -------- neighbor aggregation + BN + ReLU: float4, 4 channels/thread ------
template<int C>
__global__ __launch_bounds__(256)
void agg_kernel(const float* __restrict__ U, const float* __restrict__ V,
                const int* __restrict__ idx, const float* __restrict__ bias,
                const float* __restrict__ g, const float* __restrict__ be,
                float* __restrict__ H) {
    constexpr int CG = C / 4;
    constexpr int PPB = 256 / CG;               // 16 (C=64), 8 (C=128)
    __shared__ int sidx[PPB * KNBR];
    const int p0 = blockIdx.x * PPB;
    const int t = threadIdx.x;
    if (t < PPB * KNBR) sidx[t] = idx[(size_t)p0 * KNBR + t] * C;
    __syncthreads();
    const int lp = t / CG, c4 = (t % CG) * 4;
    const int pt = p0 + lp;
    const int b = pt >> 8;
    const float* Vb4 = V + ((size_t)(b << 8)) * C + c4;
    float4 u = *reinterpret_cast<const float4*>(&U[(size_t)pt * C + c4]);
    float4 v = *reinterpret_cast<const float4*>(&V[(size_t)pt * C + c4]);
    float4 mx = make_float4(-INFINITY, -INFINITY, -INFINITY, -INFINITY);
    float4 mn = make_float4(INFINITY, INFINITY, INFINITY, INFINITY);
    #pragma unroll
    for (int k = 0; k < KNBR; ++k) {
        float4 w = *reinterpret_cast<const float4*>(Vb4 + sidx[lp * KNBR + k]);
        mx.x = fmaxf(mx.x, w.x); mn.x = fminf(mn.x, w.x);
        mx.y = fmaxf(mx.y, w.y); mn.y = fminf(mn.y, w.y);
        mx.z = fmaxf(mx.z, w.z); mn.z = fminf(mn.z, w.z);
        mx.w = fmaxf(mx.w, w.w); mn.w = fminf(mn.w, w.w);
    }
    float4 gv = *reinterpret_cast<const float4*>(&g[c4]);
    float4 bi = *reinterpret_cast<const float4*>(&bias[c4]);
    float4 bev = *reinterpret_cast<const float4*>(&be[c4]);
    float4 o;
    { float a = gv.x * BN_SCALE_F; float m = (a >= 0.f) ? mx.x : mn.x;
      o.x = fmaxf(fmaf(a, u.x - v.x + m + bi.x, bev.x), 0.f); }
    { float a = gv.y * BN_SCALE_F; float m = (a >= 0.f) ? mx.y : mn.y;
      o.y = fmaxf(fmaf(a, u.y - v.y + m + bi.y, bev.y), 0.f); }
    { float a = gv.z * BN_SCALE_F; float m = (a >= 0.f) ? mx.z : mn.z;
      o.z = fmaxf(fmaf(a, u.z - v.z + m + bi.z, bev.z), 0.f); }
    { float a = gv.w * BN_SCALE_F; float m = (a >= 0.f) ? mx.w : mn.w;
      o.w = fmaxf(fmaf(a, u.w - v.w + m + bi.w, bev.w), 0.f); }
    *reinterpret_cast<float4*>(&H[(size_t)pt * C + c4]) = o;
}

// ------- layer-3 agg + global max pool (h >= 0), float4 --------------------
template<int C>
__global__ __launch_bounds__(256)
void agg_pool_kernel(const float* __restrict__ U, const float* __restrict__ V,
                     const int* __restrict__ idx, const float* __restrict__ bias,
                     const float* __restrict__ g, const float* __restrict__ be,
                     int* __restrict__ P) {
    constexpr int CG = C / 4;                   // 64
    constexpr int PPB = 256 / CG;               // 4
    __shared__ int sidx[PPB * KNBR];
    const int p0 = blockIdx.x * PPB;
    const int t = threadIdx.x;
    if (t < PPB * KNBR) sidx[t] = idx[(size_t)p0 * KNBR + t] * C;
    __syncthreads();
    const int lp = t / CG, c4 = (t % CG) * 4;
    const int pt = p0 + lp;
    const int b = pt >> 8;
    const float* Vb4 = V + ((size_t)(b << 8)) * C + c4;
    float4 u = *reinterpret_cast<const float4*>(&U[(size_t)pt * C + c4]);
    float4 v = *reinterpret_cast<const float4*>(&V[(size_t)pt * C + c4]);
    float4 mx = make_float4(-INFINITY, -INFINITY, -INFINITY, -INFINITY);
    float4 mn = make_float4(INFINITY, INFINITY, INFINITY, INFINITY);
    #pragma unroll
    for (int k = 0; k < KNBR; ++k) {
        float4 w = *reinterpret_cast<const float4*>(Vb4 + sidx[lp * KNBR + k]);
        mx.x = fmaxf(mx.x, w.x); mn.x = fminf(mn.x, w.x);
        mx.y = fmaxf(mx.y, w.y); mn.y = fminf(mn.y, w.y);
        mx.z = fmaxf(mx.z, w.z); mn.z = fminf(mn.z, w.z);
        mx.w = fmaxf(mx.w, w.w); mn.w = fminf(mn.w, w.w);
    }
    float4 gv = *reinterpret_cast<const float4*>(&g[c4]);
    float4 bi = *reinterpret_cast<const float4*>(&bias[c4]);
    float4 bev = *reinterpret_cast<const float4*>(&be[c4]);
    int* Pb = P + b * C + c4;
    { float a = gv.x * BN_SCALE_F; float m = (a >= 0.f) ? mx.x : mn.x;
      float h = fmaxf(fmaf(a, u.x - v.x + m + bi.x, bev.x), 0.f);
      atomicMax(Pb + 0, __float_as_int(h)); }
    { float a = gv.y * BN_SCALE_F; float m = (a >= 0.f) ? mx.y : mn.y;
      float h = fmaxf(fmaf(a, u.y - v.y + m + bi.y, bev.y), 0.f);
      atomicMax(Pb + 1, __float_as_int(h)); }
    { float a = gv.z * BN_SCALE_F; float m = (a >= 0.f) ? mx.z : mn.z;
      float h = fmaxf(fmaf(a, u.z - v.z + m + bi.z, bev.z), 0.f);
      atomicMax(Pb + 2, __float_as_int(h)); }
    { float a = gv.w * BN_SCALE_F; float m = (a >= 0.f) ? mx.w : mn.w;
      float h = fmaxf(fmaf(a, u.w - v.w + m + bi.w, bev.w), 0.f);
      atomicMax(Pb + 3, __float_as_int(h)); }
}

// ---------------- FC head --------------------------------------------------
__global__ __launch_bounds__(256)
void head_kernel(const float* __restrict__ Pp, const float* __restrict__ Wf1,
                 const float* __restrict__ bf1, const float* __restrict__ gf,
                 const float* __restrict__ bef, const float* __restrict__ Wf2,
                 const float* __restrict__ bf2, float* __restrict__ out) {
    __shared__ float ps[256];
    __shared__ float fs[128];
    const int b = blockIdx.x, t = threadIdx.x;
    ps[t] = Pp[b * 256 + t];
    __syncthreads();
    if (t < 128) {
        float acc = bf1[t];
        for (int r = 0; r < 256; ++r) acc += ps[r] * Wf1[r * 128 + t];
        float a = gf[t] * BN_SCALE_F;
        fs[t] = fmaxf(fmaf(a, acc, bef[t]), 0.f);
    }
    __syncthreads();
    if (t < 12) {
        float acc = bf2[t];
        for (int j = 0; j < 128; ++j) acc += fs[j] * Wf2[j * 12 + t];
        out[b * 12 + t] = acc;
    }
}

// ---------------- launch ----------------------------------------------------
extern "C" void kernel_launch(void* const* d_in, const int* in_sizes, int n_in,
                              void* d_out, int out_size) {
    const float* x   = (const float*)d_in[0];
    const float* W1  = (const float*)d_in[1];
    const float* b1  = (const float*)d_in[2];
    const float* g1  = (const float*)d_in[3];
    const float* be1 = (const float*)d_in[4];
    const float* W2  = (const float*)d_in[5];
    const float* b2  = (const float*)d_in[6];
    const float* g2  = (const float*)d_in[7];
    const float* be2 = (const float*)d_in[8];
    const float* W3  = (const float*)d_in[9];
    const float* b3  = (const float*)d_in[10];
    const float* g3  = (const float*)d_in[11];
    const float* be3 = (const float*)d_in[12];
    const float* Wf1 = (const float*)d_in[13];
    const float* bf1 = (const float*)d_in[14];
    const float* gf  = (const float*)d_in[15];
    const float* bef = (const float*)d_in[16];
    const float* Wf2 = (const float*)d_in[17];
    const float* bf2 = (const float*)d_in[18];
    float* out = (float*)d_out;

    float *U, *V, *h1, *h2, *p;
    int* idx;
    cudaGetSymbolAddress((void**)&U,  g_U);
    cudaGetSymbolAddress((void**)&V,  g_V);
    cudaGetSymbolAddress((void**)&h1, g_h1);
    cudaGetSymbolAddress((void**)&h2, g_h2);
    cudaGetSymbolAddress((void**)&idx, g_idx);
    cudaGetSymbolAddress((void**)&p,  g_p);

    cudaFuncSetAttribute(fatL2, cudaFuncAttributeMaxDynamicSharedMemorySize, FAT_SMEM_BYTES);
    cudaFuncSetAttribute(fatL3, cudaFuncAttributeMaxDynamicSharedMemorySize, FAT_SMEM_BYTES);

    cudaMemsetAsync(p, 0, BB * 256 * sizeof(float));   // pool init, up front

    // ---- layer 1: D=6 -> C=64 ----
    fatL1<<<128 + 1024, 256, L1_SMEM_BYTES>>>(x, W1, idx, U, V);
    agg_kernel<64><<<MM / 16, 256>>>(U, V, idx, b1, g1, be1, h1);

    // ---- layer 2: D=64 -> C=128 ----
    fatL2<<<512 + 512, 256, FAT_SMEM_BYTES>>>(h1, W2, idx, U, V);
    agg_kernel<128><<<MM / 8, 256>>>(U, V, idx, b2, g2, be2, h2);

    // ---- layer 3: D=128 -> C=256 ----
    fatL3<<<512 + 1024, 256, FAT_SMEM_BYTES>>>(h2, W3, idx, U, V);
    agg_pool_kernel<256><<<MM / 4, 256>>>(U, V, idx, b3, g3, be3, (int*)p);

    // ---- head ----
    head_kernel<<<BB, 256>>>(p, Wf1, bf1, gf, bef, Wf2, bf2, out);
}